// round 8
// baseline (speedup 1.0000x reference)
#include <cuda_runtime.h>
#include <cuda_bf16.h>
#include <cstdint>

#define HID 256
#define TPB 64

typedef unsigned int u32;

// ---- f16x2 helpers ----
__device__ __forceinline__ u32 hfma2(u32 a, u32 b, u32 c) {
    u32 d; asm("fma.rn.f16x2 %0, %1, %2, %3;" : "=r"(d) : "r"(a), "r"(b), "r"(c)); return d;
}
__device__ __forceinline__ u32 htanh2(u32 a) {
    u32 d; asm("tanh.approx.f16x2 %0, %1;" : "=r"(d) : "r"(a)); return d;
}
__device__ __forceinline__ u32 f32pair_to_h2(float a, float b) {
    u32 d; asm("cvt.rn.f16x2.f32 %0, %1, %2;" : "=r"(d) : "f"(b), "f"(a)); return d;
}
__device__ __forceinline__ void h2_to_f32pair(u32 v, float& lo, float& hi) {
    asm("{ .reg .b16 l, h;\n"
        "  mov.b32 {l, h}, %2;\n"
        "  cvt.f32.f16 %0, l;\n"
        "  cvt.f32.f16 %1, h; }"
        : "=f"(lo), "=f"(hi) : "r"(v));
}
__device__ __forceinline__ u32 h2dup(float v) {
    u32 d; asm("cvt.rn.f16x2.f32 %0, %1, %1;" : "=r"(d) : "f"(v)); return d;
}
__device__ __forceinline__ uint4 lds128(u32 addr) {
    uint4 q;
    asm volatile("ld.shared.v4.u32 {%0, %1, %2, %3}, [%4];"
                 : "=r"(q.x), "=r"(q.y), "=r"(q.z), "=r"(q.w) : "r"(addr));
    return q;
}

// one j-pair, two points (a, b) with separate register chains
#define JPAIR2(WX, WY, BB, WA, WB, A0a, A1a, A0b, A1b)          \
    {                                                           \
        u32 pa = hfma2(WX, h0a, hfma2(WY, h1a, BB));            \
        u32 pb = hfma2(WX, h0b, hfma2(WY, h1b, BB));            \
        u32 ta = htanh2(pa);                                    \
        u32 tb = htanh2(pb);                                    \
        A0a = hfma2(ta, WA, A0a);  A1a = hfma2(ta, WB, A1a);    \
        A0b = hfma2(tb, WA, A0b);  A1b = hfma2(tb, WB, A1b);    \
    }

// SMEM: per superblock (4 j-pairs = 8 hidden units), 20 u32 = 5x LDS.128
__device__ __forceinline__ void geval2(float y0a, float y1a, float y0b, float y1b,
                                       u32 wbase, float hb20, float hb21,
                                       float& o0a, float& o1a,
                                       float& o0b, float& o1b)
{
    u32 h0a = h2dup(y0a), h1a = h2dup(y1a);
    u32 h0b = h2dup(y0b), h1b = h2dup(y1b);
    u32 a0Aa = 0u, a0Ba = 0u, a1Aa = 0u, a1Ba = 0u;
    u32 a0Ab = 0u, a0Bb = 0u, a1Ab = 0u, a1Bb = 0u;
    u32 addr = wbase;
#pragma unroll
    for (int blk = 0; blk < HID / 8; blk++, addr += 80) {
        uint4 q0 = lds128(addr);
        uint4 q1 = lds128(addr + 16);
        uint4 q2 = lds128(addr + 32);
        uint4 q3 = lds128(addr + 48);
        uint4 q4 = lds128(addr + 64);
        JPAIR2(q0.x, q0.y, q0.z, q0.w, q1.x, a0Aa, a1Aa, a0Ab, a1Ab);
        JPAIR2(q1.y, q1.z, q1.w, q2.x, q2.y, a0Ba, a1Ba, a0Bb, a1Bb);
        JPAIR2(q2.z, q2.w, q3.x, q3.y, q3.z, a0Aa, a1Aa, a0Ab, a1Ab);
        JPAIR2(q3.w, q4.x, q4.y, q4.z, q4.w, a0Ba, a1Ba, a0Bb, a1Bb);
    }
    float p, q, r, s;
    h2_to_f32pair(a0Aa, p, q);  h2_to_f32pair(a0Ba, r, s);
    o0a = ((p + q) + (r + s)) + hb20;
    h2_to_f32pair(a1Aa, p, q);  h2_to_f32pair(a1Ba, r, s);
    o1a = ((p + q) + (r + s)) + hb21;
    h2_to_f32pair(a0Ab, p, q);  h2_to_f32pair(a0Bb, r, s);
    o0b = ((p + q) + (r + s)) + hb20;
    h2_to_f32pair(a1Ab, p, q);  h2_to_f32pair(a1Bb, r, s);
    o1b = ((p + q) + (r + s)) + hb21;
}

__global__ __launch_bounds__(TPB)
void node_rk4_kernel(const float* __restrict__ x,
                     const float* __restrict__ W1,
                     const float* __restrict__ b1,
                     const float* __restrict__ W2,
                     const float* __restrict__ b2,
                     const float* __restrict__ Wf,
                     const float* __restrict__ bf,
                     const int*   __restrict__ tptr,
                     float* __restrict__ out,
                     int B)
{
    __shared__ u32   s_w[(HID / 8) * 20];
    __shared__ float sc[8];
    __shared__ int   s_nsteps;

    const float h = 0.01f;
    const int tid = threadIdx.x;

    for (int p = tid; p < HID / 2; p += TPB) {
        int j0 = 2 * p, j1 = 2 * p + 1;
        int base = (p >> 2) * 20 + (p & 3) * 5;
        s_w[base + 0] = f32pair_to_h2(W1[j0],       W1[j1]);
        s_w[base + 1] = f32pair_to_h2(W1[HID + j0], W1[HID + j1]);
        s_w[base + 2] = f32pair_to_h2(b1[j0],       b1[j1]);
        s_w[base + 3] = f32pair_to_h2(h * W2[2 * j0],     h * W2[2 * j1]);
        s_w[base + 4] = f32pair_to_h2(h * W2[2 * j0 + 1], h * W2[2 * j1 + 1]);
    }
    if (tid == 0) {
        sc[0] = h * b2[0]; sc[1] = h * b2[1];
        sc[2] = Wf[0]; sc[3] = Wf[1]; sc[4] = Wf[2]; sc[5] = Wf[3];
        sc[6] = bf[0]; sc[7] = bf[1];

        int tv = tptr[0];
        if (tv <= 0 || tv > 100000) tv = (int)__int_as_float(tv);
        double tf = 0.1 * (double)tv;
        double tt = 0.0;
        int n = 0;
        while (tt <= tf) { n++; tt += 0.01; }
        s_nsteps = n;
    }
    __syncthreads();

    u32 wbase = (u32)__cvta_generic_to_shared(s_w);

    const int i = blockIdx.x * TPB + tid;     // pair index: points 2i, 2i+1
    const int npairs = B >> 1;
    if (i >= npairs) return;

    float4 xv = reinterpret_cast<const float4*>(x)[i];
    float y0a = xv.x, y1a = xv.y;    // point A
    float y0b = xv.z, y1b = xv.w;    // point B

    const int nsteps = s_nsteps;
    const float hb20 = sc[0], hb21 = sc[1];

    for (int s = 0; s < nsteps; s++) {
        float k10a, k11a, k20a, k21a, k30a, k31a, k40a, k41a;
        float k10b, k11b, k20b, k21b, k30b, k31b, k40b, k41b;

        geval2(y0a, y1a, y0b, y1b, wbase, hb20, hb21,
               k10a, k11a, k10b, k11b);
        geval2(__fmaf_rn(0.5f, k10a, y0a), __fmaf_rn(0.5f, k11a, y1a),
               __fmaf_rn(0.5f, k10b, y0b), __fmaf_rn(0.5f, k11b, y1b),
               wbase, hb20, hb21, k20a, k21a, k20b, k21b);
        geval2(__fmaf_rn(0.5f, k20a, y0a), __fmaf_rn(0.5f, k21a, y1a),
               __fmaf_rn(0.5f, k20b, y0b), __fmaf_rn(0.5f, k21b, y1b),
               wbase, hb20, hb21, k30a, k31a, k30b, k31b);
        geval2(y0a + k30a, y1a + k31a, y0b + k30b, y1b + k31b,
               wbase, hb20, hb21, k40a, k41a, k40b, k41b);

        y0a = __fmaf_rn(k10a + 2.0f * (k20a + k30a) + k40a, (1.0f / 6.0f), y0a);
        y1a = __fmaf_rn(k11a + 2.0f * (k21a + k31a) + k41a, (1.0f / 6.0f), y1a);
        y0b = __fmaf_rn(k10b + 2.0f * (k20b + k30b) + k40b, (1.0f / 6.0f), y0b);
        y1b = __fmaf_rn(k11b + 2.0f * (k21b + k31b) + k41b, (1.0f / 6.0f), y1b);
    }

    const float wf00 = sc[2], wf01 = sc[3], wf10 = sc[4], wf11 = sc[5];
    const float bf0 = sc[6], bf1 = sc[7];

    float l0a = __fmaf_rn(y0a, wf00, __fmaf_rn(y1a, wf10, bf0));
    float l1a = __fmaf_rn(y0a, wf01, __fmaf_rn(y1a, wf11, bf1));
    float l0b = __fmaf_rn(y0b, wf00, __fmaf_rn(y1b, wf10, bf0));
    float l1b = __fmaf_rn(y0b, wf01, __fmaf_rn(y1b, wf11, bf1));

    float ma = fmaxf(l0a, l1a), mb = fmaxf(l0b, l1b);
    float e0a = __expf(l0a - ma), e1a = __expf(l1a - ma);
    float e0b = __expf(l0b - mb), e1b = __expf(l1b - mb);
    float ia = 1.0f / (e0a + e1a), ib = 1.0f / (e0b + e1b);

    float4* outL = reinterpret_cast<float4*>(out);
    float4* outP = reinterpret_cast<float4*>(out + 2 * B);
    outL[i] = make_float4(l0a, l1a, l0b, l1b);
    outP[i] = make_float4(e0a * ia, e1a * ia, e0b * ib, e1b * ib);
}

extern "C" void kernel_launch(void* const* d_in, const int* in_sizes, int n_in,
                              void* d_out, int out_size)
{
    const float* x  = (const float*)d_in[0];
    const float* W1 = (const float*)d_in[1];
    const float* b1 = (const float*)d_in[2];
    const float* W2 = (const float*)d_in[3];
    const float* b2 = (const float*)d_in[4];
    const float* Wf = (const float*)d_in[5];
    const float* bf = (const float*)d_in[6];
    const int*   t  = (const int*)d_in[7];
    float* out = (float*)d_out;

    const int B = in_sizes[0] / 2;
    const int npairs = B / 2;
    const int grid = (npairs + TPB - 1) / TPB;
    node_rk4_kernel<<<grid, TPB>>>(x, W1, b1, W2, b2, Wf, bf, t, out, B);
}

// round 9
// speedup vs baseline: 6.0080x; 6.0080x over previous
#include <cuda_runtime.h>
#include <cuda_bf16.h>
#include <cstdint>

#define HID 256
#define TPB 64

typedef unsigned int u32;

// ---- f16x2 helpers ----
__device__ __forceinline__ u32 hfma2(u32 a, u32 b, u32 c) {
    u32 d; asm("fma.rn.f16x2 %0, %1, %2, %3;" : "=r"(d) : "r"(a), "r"(b), "r"(c)); return d;
}
__device__ __forceinline__ u32 htanh2(u32 a) {
    u32 d; asm("tanh.approx.f16x2 %0, %1;" : "=r"(d) : "r"(a)); return d;
}
__device__ __forceinline__ u32 f32pair_to_h2(float a, float b) {
    u32 d; asm("cvt.rn.f16x2.f32 %0, %1, %2;" : "=r"(d) : "f"(b), "f"(a)); return d;
}
__device__ __forceinline__ void h2_to_f32pair(u32 v, float& lo, float& hi) {
    asm("{ .reg .b16 l, h;\n"
        "  mov.b32 {l, h}, %2;\n"
        "  cvt.f32.f16 %0, l;\n"
        "  cvt.f32.f16 %1, h; }"
        : "=f"(lo), "=f"(hi) : "r"(v));
}
__device__ __forceinline__ u32 h2dup(float v) {
    u32 d; asm("cvt.rn.f16x2.f32 %0, %1, %1;" : "=r"(d) : "f"(v)); return d;
}
__device__ __forceinline__ uint4 lds128(u32 addr) {
    uint4 q;
    asm volatile("ld.shared.v4.u32 {%0, %1, %2, %3}, [%4];"
                 : "=r"(q.x), "=r"(q.y), "=r"(q.z), "=r"(q.w) : "r"(addr));
    return q;
}

// one j-pair, two points (a, b) with separate register chains
#define JPAIR2(WX, WY, BB, WA, WB, A0a, A1a, A0b, A1b)          \
    {                                                           \
        u32 pa = hfma2(WX, h0a, hfma2(WY, h1a, BB));            \
        u32 pb = hfma2(WX, h0b, hfma2(WY, h1b, BB));            \
        u32 ta = htanh2(pa);                                    \
        u32 tb = htanh2(pb);                                    \
        A0a = hfma2(ta, WA, A0a);  A1a = hfma2(ta, WB, A1a);    \
        A0b = hfma2(tb, WA, A0b);  A1b = hfma2(tb, WB, A1b);    \
    }

// SMEM: per superblock (4 j-pairs = 8 hidden units), 20 u32 = 5x LDS.128
__device__ __forceinline__ void geval2(float y0a, float y1a, float y0b, float y1b,
                                       u32 wbase, float hb20, float hb21,
                                       float& o0a, float& o1a,
                                       float& o0b, float& o1b)
{
    u32 h0a = h2dup(y0a), h1a = h2dup(y1a);
    u32 h0b = h2dup(y0b), h1b = h2dup(y1b);
    u32 a0Aa = 0u, a0Ba = 0u, a1Aa = 0u, a1Ba = 0u;
    u32 a0Ab = 0u, a0Bb = 0u, a1Ab = 0u, a1Bb = 0u;
    u32 addr = wbase;
#pragma unroll 4
    for (int blk = 0; blk < HID / 8; blk++, addr += 80) {
        uint4 q0 = lds128(addr);
        uint4 q1 = lds128(addr + 16);
        uint4 q2 = lds128(addr + 32);
        uint4 q3 = lds128(addr + 48);
        uint4 q4 = lds128(addr + 64);
        JPAIR2(q0.x, q0.y, q0.z, q0.w, q1.x, a0Aa, a1Aa, a0Ab, a1Ab);
        JPAIR2(q1.y, q1.z, q1.w, q2.x, q2.y, a0Ba, a1Ba, a0Bb, a1Bb);
        JPAIR2(q2.z, q2.w, q3.x, q3.y, q3.z, a0Aa, a1Aa, a0Ab, a1Ab);
        JPAIR2(q3.w, q4.x, q4.y, q4.z, q4.w, a0Ba, a1Ba, a0Bb, a1Bb);
    }
    float p, q, r, s;
    h2_to_f32pair(a0Aa, p, q);  h2_to_f32pair(a0Ba, r, s);
    o0a = ((p + q) + (r + s)) + hb20;
    h2_to_f32pair(a1Aa, p, q);  h2_to_f32pair(a1Ba, r, s);
    o1a = ((p + q) + (r + s)) + hb21;
    h2_to_f32pair(a0Ab, p, q);  h2_to_f32pair(a0Bb, r, s);
    o0b = ((p + q) + (r + s)) + hb20;
    h2_to_f32pair(a1Ab, p, q);  h2_to_f32pair(a1Bb, r, s);
    o1b = ((p + q) + (r + s)) + hb21;
}

__global__ __launch_bounds__(TPB)
void node_rk4_kernel(const float* __restrict__ x,
                     const float* __restrict__ W1,
                     const float* __restrict__ b1,
                     const float* __restrict__ W2,
                     const float* __restrict__ b2,
                     const float* __restrict__ Wf,
                     const float* __restrict__ bf,
                     const int*   __restrict__ tptr,
                     float* __restrict__ out,
                     int B)
{
    __shared__ u32   s_w[(HID / 8) * 20];
    __shared__ float sc[8];
    __shared__ int   s_nsteps;

    const float h = 0.01f;
    const int tid = threadIdx.x;

    for (int p = tid; p < HID / 2; p += TPB) {
        int j0 = 2 * p, j1 = 2 * p + 1;
        int base = (p >> 2) * 20 + (p & 3) * 5;
        s_w[base + 0] = f32pair_to_h2(W1[j0],       W1[j1]);
        s_w[base + 1] = f32pair_to_h2(W1[HID + j0], W1[HID + j1]);
        s_w[base + 2] = f32pair_to_h2(b1[j0],       b1[j1]);
        s_w[base + 3] = f32pair_to_h2(h * W2[2 * j0],     h * W2[2 * j1]);
        s_w[base + 4] = f32pair_to_h2(h * W2[2 * j0 + 1], h * W2[2 * j1 + 1]);
    }
    if (tid == 0) {
        sc[0] = h * b2[0]; sc[1] = h * b2[1];
        sc[2] = Wf[0]; sc[3] = Wf[1]; sc[4] = Wf[2]; sc[5] = Wf[3];
        sc[6] = bf[0]; sc[7] = bf[1];

        int tv = tptr[0];
        if (tv <= 0 || tv > 100000) tv = (int)__int_as_float(tv);
        double tf = 0.1 * (double)tv;
        double tt = 0.0;
        int n = 0;
        while (tt <= tf) { n++; tt += 0.01; }
        s_nsteps = n;
    }
    __syncthreads();

    u32 wbase = (u32)__cvta_generic_to_shared(s_w);

    const int i = blockIdx.x * TPB + tid;     // pair index: points 2i, 2i+1
    const int npairs = B >> 1;
    if (i >= npairs) return;

    float4 xv = reinterpret_cast<const float4*>(x)[i];
    float y0a = xv.x, y1a = xv.y;    // point A
    float y0b = xv.z, y1b = xv.w;    // point B

    const int nsteps = s_nsteps;
    const float hb20 = sc[0], hb21 = sc[1];

    for (int s = 0; s < nsteps; s++) {
        float k10a, k11a, k20a, k21a, k30a, k31a, k40a, k41a;
        float k10b, k11b, k20b, k21b, k30b, k31b, k40b, k41b;

        geval2(y0a, y1a, y0b, y1b, wbase, hb20, hb21,
               k10a, k11a, k10b, k11b);
        geval2(__fmaf_rn(0.5f, k10a, y0a), __fmaf_rn(0.5f, k11a, y1a),
               __fmaf_rn(0.5f, k10b, y0b), __fmaf_rn(0.5f, k11b, y1b),
               wbase, hb20, hb21, k20a, k21a, k20b, k21b);
        geval2(__fmaf_rn(0.5f, k20a, y0a), __fmaf_rn(0.5f, k21a, y1a),
               __fmaf_rn(0.5f, k20b, y0b), __fmaf_rn(0.5f, k21b, y1b),
               wbase, hb20, hb21, k30a, k31a, k30b, k31b);
        geval2(y0a + k30a, y1a + k31a, y0b + k30b, y1b + k31b,
               wbase, hb20, hb21, k40a, k41a, k40b, k41b);

        y0a = __fmaf_rn(k10a + 2.0f * (k20a + k30a) + k40a, (1.0f / 6.0f), y0a);
        y1a = __fmaf_rn(k11a + 2.0f * (k21a + k31a) + k41a, (1.0f / 6.0f), y1a);
        y0b = __fmaf_rn(k10b + 2.0f * (k20b + k30b) + k40b, (1.0f / 6.0f), y0b);
        y1b = __fmaf_rn(k11b + 2.0f * (k21b + k31b) + k41b, (1.0f / 6.0f), y1b);
    }

    const float wf00 = sc[2], wf01 = sc[3], wf10 = sc[4], wf11 = sc[5];
    const float bf0 = sc[6], bf1 = sc[7];

    float l0a = __fmaf_rn(y0a, wf00, __fmaf_rn(y1a, wf10, bf0));
    float l1a = __fmaf_rn(y0a, wf01, __fmaf_rn(y1a, wf11, bf1));
    float l0b = __fmaf_rn(y0b, wf00, __fmaf_rn(y1b, wf10, bf0));
    float l1b = __fmaf_rn(y0b, wf01, __fmaf_rn(y1b, wf11, bf1));

    float ma = fmaxf(l0a, l1a), mb = fmaxf(l0b, l1b);
    float e0a = __expf(l0a - ma), e1a = __expf(l1a - ma);
    float e0b = __expf(l0b - mb), e1b = __expf(l1b - mb);
    float ia = 1.0f / (e0a + e1a), ib = 1.0f / (e0b + e1b);

    float4* outL = reinterpret_cast<float4*>(out);
    float4* outP = reinterpret_cast<float4*>(out + 2 * B);
    outL[i] = make_float4(l0a, l1a, l0b, l1b);
    outP[i] = make_float4(e0a * ia, e1a * ia, e0b * ib, e1b * ib);
}

extern "C" void kernel_launch(void* const* d_in, const int* in_sizes, int n_in,
                              void* d_out, int out_size)
{
    const float* x  = (const float*)d_in[0];
    const float* W1 = (const float*)d_in[1];
    const float* b1 = (const float*)d_in[2];
    const float* W2 = (const float*)d_in[3];
    const float* b2 = (const float*)d_in[4];
    const float* Wf = (const float*)d_in[5];
    const float* bf = (const float*)d_in[6];
    const int*   t  = (const int*)d_in[7];
    float* out = (float*)d_out;

    const int B = in_sizes[0] / 2;
    const int npairs = B / 2;
    const int grid = (npairs + TPB - 1) / TPB;
    node_rk4_kernel<<<grid, TPB>>>(x, W1, b1, W2, b2, Wf, bf, t, out, B);
}

// round 10
// speedup vs baseline: 7.0802x; 1.1785x over previous
#include <cuda_runtime.h>
#include <cuda_bf16.h>
#include <cstdint>

#define HID 256
#define TPB 128
#define NSB (HID / 8)   // 32 superblocks of 8 hidden units

typedef unsigned int u32;

// ---- f16x2 helpers ----
__device__ __forceinline__ u32 hfma2(u32 a, u32 b, u32 c) {
    u32 d; asm("fma.rn.f16x2 %0, %1, %2, %3;" : "=r"(d) : "r"(a), "r"(b), "r"(c)); return d;
}
__device__ __forceinline__ u32 htanh2(u32 a) {
    u32 d; asm("tanh.approx.f16x2 %0, %1;" : "=r"(d) : "r"(a)); return d;
}
__device__ __forceinline__ u32 f32pair_to_h2(float a, float b) {
    u32 d; asm("cvt.rn.f16x2.f32 %0, %1, %2;" : "=r"(d) : "f"(b), "f"(a)); return d;
}
__device__ __forceinline__ void h2_to_f32pair(u32 v, float& lo, float& hi) {
    asm("{ .reg .b16 l, h;\n"
        "  mov.b32 {l, h}, %2;\n"
        "  cvt.f32.f16 %0, l;\n"
        "  cvt.f32.f16 %1, h; }"
        : "=f"(lo), "=f"(hi) : "r"(v));
}
__device__ __forceinline__ u32 h2dup(float v) {
    u32 d; asm("cvt.rn.f16x2.f32 %0, %1, %1;" : "=r"(d) : "f"(v)); return d;
}
__device__ __forceinline__ uint4 lds128(u32 addr) {
    uint4 q;
    asm volatile("ld.shared.v4.u32 {%0, %1, %2, %3}, [%4];"
                 : "=r"(q.x), "=r"(q.y), "=r"(q.z), "=r"(q.w) : "r"(addr));
    return q;
}

// one j-pair: 3 HFMA2 + 1 XU; h0/h1 are the point's coords duplicated in lanes
#define JPAIR(WX, WY, BB, WA, WB, A0, A1)                \
    {                                                    \
        u32 pre = hfma2(WX, h0, hfma2(WY, h1, BB));      \
        u32 t = htanh2(pre);                             \
        A0 = hfma2(t, WA, A0);                           \
        A1 = hfma2(t, WB, A1);                           \
    }

// SMEM: per superblock (4 j-pairs = 8 hidden units), 20 u32 = 5x LDS.128,
// padded by one superblock so the prefetch never reads out of bounds.
__device__ __forceinline__ void geval1(float y0, float y1, u32 wbase,
                                       float hb20, float hb21,
                                       float& o0, float& o1)
{
    u32 h0 = h2dup(y0);
    u32 h1 = h2dup(y1);
    u32 a0A = 0u, a0B = 0u, a1A = 0u, a1B = 0u;
    u32 addr = wbase;

    // prefetch superblock 0
    uint4 p0 = lds128(addr);
    uint4 p1 = lds128(addr + 16);
    uint4 p2 = lds128(addr + 32);
    uint4 p3 = lds128(addr + 48);
    uint4 p4 = lds128(addr + 64);

#pragma unroll 4
    for (int blk = 0; blk < NSB; blk++) {
        uint4 c0 = p0, c1 = p1, c2 = p2, c3 = p3, c4 = p4;
        addr += 80;
        // prefetch next superblock (padded; blk==NSB-1 load is discarded)
        p0 = lds128(addr);
        p1 = lds128(addr + 16);
        p2 = lds128(addr + 32);
        p3 = lds128(addr + 48);
        p4 = lds128(addr + 64);

        JPAIR(c0.x, c0.y, c0.z, c0.w, c1.x, a0A, a1A);
        JPAIR(c1.y, c1.z, c1.w, c2.x, c2.y, a0B, a1B);
        JPAIR(c2.z, c2.w, c3.x, c3.y, c3.z, a0A, a1A);
        JPAIR(c3.w, c4.x, c4.y, c4.z, c4.w, a0B, a1B);
    }
    float p, q, r, s;
    h2_to_f32pair(a0A, p, q);
    h2_to_f32pair(a0B, r, s);
    o0 = ((p + q) + (r + s)) + hb20;
    h2_to_f32pair(a1A, p, q);
    h2_to_f32pair(a1B, r, s);
    o1 = ((p + q) + (r + s)) + hb21;
}

__global__ __launch_bounds__(TPB, 7)
void node_rk4_kernel(const float* __restrict__ x,
                     const float* __restrict__ W1,
                     const float* __restrict__ b1,
                     const float* __restrict__ W2,
                     const float* __restrict__ b2,
                     const float* __restrict__ Wf,
                     const float* __restrict__ bf,
                     const int*   __restrict__ tptr,
                     float* __restrict__ out,
                     int B)
{
    __shared__ u32   s_w[(NSB + 1) * 20];   // +1 superblock pad for prefetch
    __shared__ float sc[8];
    __shared__ int   s_nsteps;

    const float h = 0.01f;
    const int tid = threadIdx.x;

    // j-pair p covers hidden units 2p, 2p+1.
    if (tid < HID / 2) {
        int p = tid;
        int j0 = 2 * p, j1 = 2 * p + 1;
        int base = (p >> 2) * 20 + (p & 3) * 5;
        s_w[base + 0] = f32pair_to_h2(W1[j0],       W1[j1]);
        s_w[base + 1] = f32pair_to_h2(W1[HID + j0], W1[HID + j1]);
        s_w[base + 2] = f32pair_to_h2(b1[j0],       b1[j1]);
        s_w[base + 3] = f32pair_to_h2(h * W2[2 * j0],     h * W2[2 * j1]);
        s_w[base + 4] = f32pair_to_h2(h * W2[2 * j0 + 1], h * W2[2 * j1 + 1]);
    }
    // zero the pad superblock
    if (tid >= HID / 2 && tid < HID / 2 + 20) {
        s_w[NSB * 20 + (tid - HID / 2)] = 0u;
    }
    if (tid == 0) {
        sc[0] = h * b2[0]; sc[1] = h * b2[1];
        sc[2] = Wf[0]; sc[3] = Wf[1]; sc[4] = Wf[2]; sc[5] = Wf[3];
        sc[6] = bf[0]; sc[7] = bf[1];

        int tv = tptr[0];
        if (tv <= 0 || tv > 100000) tv = (int)__int_as_float(tv);
        double tf = 0.1 * (double)tv;
        double tt = 0.0;
        int n = 0;
        while (tt <= tf) { n++; tt += 0.01; }
        s_nsteps = n;
    }
    __syncthreads();

    u32 wbase = (u32)__cvta_generic_to_shared(s_w);

    const int i = blockIdx.x * TPB + tid;
    if (i >= B) return;

    float2 xv = reinterpret_cast<const float2*>(x)[i];
    float y0 = xv.x, y1 = xv.y;

    const int nsteps = s_nsteps;
    const float hb20 = sc[0], hb21 = sc[1];

    for (int s = 0; s < nsteps; s++) {
        float k10, k11, k20, k21, k30, k31, k40, k41;
        geval1(y0, y1, wbase, hb20, hb21, k10, k11);
        geval1(__fmaf_rn(0.5f, k10, y0), __fmaf_rn(0.5f, k11, y1),
               wbase, hb20, hb21, k20, k21);
        geval1(__fmaf_rn(0.5f, k20, y0), __fmaf_rn(0.5f, k21, y1),
               wbase, hb20, hb21, k30, k31);
        geval1(y0 + k30, y1 + k31, wbase, hb20, hb21, k40, k41);

        y0 = __fmaf_rn((k10 + 2.0f * (k20 + k30) + k40), (1.0f / 6.0f), y0);
        y1 = __fmaf_rn((k11 + 2.0f * (k21 + k31) + k41), (1.0f / 6.0f), y1);
    }

    float l0 = __fmaf_rn(y0, sc[2], __fmaf_rn(y1, sc[4], sc[6]));
    float l1 = __fmaf_rn(y0, sc[3], __fmaf_rn(y1, sc[5], sc[7]));

    float m  = fmaxf(l0, l1);
    float e0 = __expf(l0 - m);
    float e1 = __expf(l1 - m);
    float inv = 1.0f / (e0 + e1);

    float2* outL = reinterpret_cast<float2*>(out);
    float2* outP = reinterpret_cast<float2*>(out + 2 * B);
    outL[i] = make_float2(l0, l1);
    outP[i] = make_float2(e0 * inv, e1 * inv);
}

extern "C" void kernel_launch(void* const* d_in, const int* in_sizes, int n_in,
                              void* d_out, int out_size)
{
    const float* x  = (const float*)d_in[0];
    const float* W1 = (const float*)d_in[1];
    const float* b1 = (const float*)d_in[2];
    const float* W2 = (const float*)d_in[3];
    const float* b2 = (const float*)d_in[4];
    const float* Wf = (const float*)d_in[5];
    const float* bf = (const float*)d_in[6];
    const int*   t  = (const int*)d_in[7];
    float* out = (float*)d_out;

    const int B = in_sizes[0] / 2;
    const int grid = (B + TPB - 1) / TPB;
    node_rk4_kernel<<<grid, TPB>>>(x, W1, b1, W2, b2, Wf, bf, t, out, B);
}